// round 3
// baseline (speedup 1.0000x reference)
#include <cuda_runtime.h>
#include <cstddef>

// ---------------------------------------------------------------------------
// Problem constants (shapes are fixed by the reference):
//   word_embs: (8, 2048, 1024) f32   -> 16,777,216 elems
//   sent_embs: (8,  512, 1024) f32   ->  4,194,304 elems
//   W:         (1024, 1024)    f32   ->  1,048,576 elems
// Output (flattened tuple): combination (8,2048,2048) then g (8,2048,1024)
// ---------------------------------------------------------------------------

#define B_      8
#define S_      2048
#define NSENT_  512
#define E_      1024

#define TILE_M 128
#define TILE_N 128
#define TILE_K 16
#define NTHREADS 256   // (128/8)*(128/8)

// 32 MB scratch for attention scores (8 x 2048 x 512 f32).
__device__ float g_scores[B_ * S_ * NSENT_];

// ---------------------------------------------------------------------------
// C[m,n] = sum_k A[m,k] * B[n,k]   (both operands K-contiguous, "NT")
// Batched via blockIdx.z with element-strides. If C==nullptr, writes g_scores.
// All dims assumed tile-divisible (true for every call here).
// ---------------------------------------------------------------------------
__global__ __launch_bounds__(NTHREADS)
void sgemm_nt(const float* __restrict__ A, const float* __restrict__ Bm,
              float* __restrict__ C,
              int lda, int ldb, int ldc, int K,
              size_t aBatch, size_t bBatch, size_t cBatch)
{
    __shared__ float As[TILE_K][TILE_M + 4];
    __shared__ float Bs[TILE_K][TILE_N + 4];

    float* Cbase = C ? C : g_scores;

    const float* Ab = A     + (size_t)blockIdx.z * aBatch + (size_t)blockIdx.y * TILE_M * lda;
    const float* Bb = Bm    + (size_t)blockIdx.z * bBatch + (size_t)blockIdx.x * TILE_N * ldb;
    float*       Cb = Cbase + (size_t)blockIdx.z * cBatch + (size_t)blockIdx.y * TILE_M * ldc
                            + (size_t)blockIdx.x * TILE_N;

    const int tid   = threadIdx.x;
    const int ldRow = tid >> 2;          // 0..63
    const int ldK   = (tid & 3) * 4;     // 0,4,8,12

    const int tCol  = tid & 15;          // 0..15
    const int tRow  = tid >> 4;          // 0..15

    float acc[8][8];
#pragma unroll
    for (int i = 0; i < 8; i++)
#pragma unroll
        for (int j = 0; j < 8; j++) acc[i][j] = 0.f;

    for (int k0 = 0; k0 < K; k0 += TILE_K) {
#pragma unroll
        for (int r = 0; r < 2; r++) {
            const int row = ldRow + 64 * r;
            float4 a = *reinterpret_cast<const float4*>(Ab + (size_t)row * lda + k0 + ldK);
            As[ldK + 0][row] = a.x;
            As[ldK + 1][row] = a.y;
            As[ldK + 2][row] = a.z;
            As[ldK + 3][row] = a.w;
            float4 b = *reinterpret_cast<const float4*>(Bb + (size_t)row * ldb + k0 + ldK);
            Bs[ldK + 0][row] = b.x;
            Bs[ldK + 1][row] = b.y;
            Bs[ldK + 2][row] = b.z;
            Bs[ldK + 3][row] = b.w;
        }
        __syncthreads();

#pragma unroll
        for (int k = 0; k < TILE_K; k++) {
            float4 m0 = *reinterpret_cast<const float4*>(&As[k][tRow * 8]);
            float4 m1 = *reinterpret_cast<const float4*>(&As[k][tRow * 8 + 4]);
            float4 n0 = *reinterpret_cast<const float4*>(&Bs[k][tCol * 8]);
            float4 n1 = *reinterpret_cast<const float4*>(&Bs[k][tCol * 8 + 4]);
            float rm[8] = {m0.x, m0.y, m0.z, m0.w, m1.x, m1.y, m1.z, m1.w};
            float rn[8] = {n0.x, n0.y, n0.z, n0.w, n1.x, n1.y, n1.z, n1.w};
#pragma unroll
            for (int i = 0; i < 8; i++)
#pragma unroll
                for (int j = 0; j < 8; j++)
                    acc[i][j] = fmaf(rm[i], rn[j], acc[i][j]);
        }
        __syncthreads();
    }

#pragma unroll
    for (int i = 0; i < 8; i++) {
        float* crow = Cb + (size_t)(tRow * 8 + i) * ldc + tCol * 8;
        *reinterpret_cast<float4*>(crow)     = make_float4(acc[i][0], acc[i][1], acc[i][2], acc[i][3]);
        *reinterpret_cast<float4*>(crow + 4) = make_float4(acc[i][4], acc[i][5], acc[i][6], acc[i][7]);
    }
}

// ---------------------------------------------------------------------------
// C[m,n] = sum_k A[m,k] * B[k,n]   ("NN"), dual-output epilogue.
// If A==nullptr, reads g_scores. Writes both C1 (combination 2nd half) and C2 (g).
// ---------------------------------------------------------------------------
__global__ __launch_bounds__(NTHREADS)
void sgemm_nn_dual(const float* __restrict__ A, const float* __restrict__ Bm,
                   float* __restrict__ C1, float* __restrict__ C2,
                   int lda, int ldb, int ldc1, int ldc2, int K,
                   size_t aBatch, size_t bBatch, size_t c1Batch, size_t c2Batch)
{
    __shared__ float As[TILE_K][TILE_M + 4];
    __shared__ float Bs[TILE_K][TILE_N];

    const float* Abase = A ? A : g_scores;

    const float* Ab = Abase + (size_t)blockIdx.z * aBatch + (size_t)blockIdx.y * TILE_M * lda;
    const float* Bb = Bm    + (size_t)blockIdx.z * bBatch + (size_t)blockIdx.x * TILE_N;
    float*       C1b = C1 + (size_t)blockIdx.z * c1Batch + (size_t)blockIdx.y * TILE_M * ldc1
                          + (size_t)blockIdx.x * TILE_N;
    float*       C2b = C2 + (size_t)blockIdx.z * c2Batch + (size_t)blockIdx.y * TILE_M * ldc2
                          + (size_t)blockIdx.x * TILE_N;

    const int tid    = threadIdx.x;
    const int aRow   = tid >> 2;          // 0..63
    const int aK     = (tid & 3) * 4;     // 0,4,8,12
    const int bRow   = tid >> 5;          // 0..7
    const int bCol4  = (tid & 31) * 4;    // 0..124

    const int tCol = tid & 15;
    const int tRow = tid >> 4;

    float acc[8][8];
#pragma unroll
    for (int i = 0; i < 8; i++)
#pragma unroll
        for (int j = 0; j < 8; j++) acc[i][j] = 0.f;

    for (int k0 = 0; k0 < K; k0 += TILE_K) {
#pragma unroll
        for (int r = 0; r < 2; r++) {
            const int row = aRow + 64 * r;
            float4 a = *reinterpret_cast<const float4*>(Ab + (size_t)row * lda + k0 + aK);
            As[aK + 0][row] = a.x;
            As[aK + 1][row] = a.y;
            As[aK + 2][row] = a.z;
            As[aK + 3][row] = a.w;
        }
#pragma unroll
        for (int r = 0; r < 2; r++) {
            const int krow = bRow + 8 * r;
            float4 b = *reinterpret_cast<const float4*>(Bb + (size_t)(k0 + krow) * ldb + bCol4);
            *reinterpret_cast<float4*>(&Bs[krow][bCol4]) = b;
        }
        __syncthreads();

#pragma unroll
        for (int k = 0; k < TILE_K; k++) {
            float4 m0 = *reinterpret_cast<const float4*>(&As[k][tRow * 8]);
            float4 m1 = *reinterpret_cast<const float4*>(&As[k][tRow * 8 + 4]);
            float4 n0 = *reinterpret_cast<const float4*>(&Bs[k][tCol * 8]);
            float4 n1 = *reinterpret_cast<const float4*>(&Bs[k][tCol * 8 + 4]);
            float rm[8] = {m0.x, m0.y, m0.z, m0.w, m1.x, m1.y, m1.z, m1.w};
            float rn[8] = {n0.x, n0.y, n0.z, n0.w, n1.x, n1.y, n1.z, n1.w};
#pragma unroll
            for (int i = 0; i < 8; i++)
#pragma unroll
                for (int j = 0; j < 8; j++)
                    acc[i][j] = fmaf(rm[i], rn[j], acc[i][j]);
        }
        __syncthreads();
    }

#pragma unroll
    for (int i = 0; i < 8; i++) {
        float4 lo = make_float4(acc[i][0], acc[i][1], acc[i][2], acc[i][3]);
        float4 hi = make_float4(acc[i][4], acc[i][5], acc[i][6], acc[i][7]);
        float* c1row = C1b + (size_t)(tRow * 8 + i) * ldc1 + tCol * 8;
        float* c2row = C2b + (size_t)(tRow * 8 + i) * ldc2 + tCol * 8;
        *reinterpret_cast<float4*>(c1row)     = lo;
        *reinterpret_cast<float4*>(c1row + 4) = hi;
        *reinterpret_cast<float4*>(c2row)     = lo;
        *reinterpret_cast<float4*>(c2row + 4) = hi;
    }
}

// ---------------------------------------------------------------------------
// In-place softmax over last dim (512) of g_scores. One 256-thread block/row.
// Numerically stable (max-subtracted), matching jax.nn.softmax.
// ---------------------------------------------------------------------------
__global__ __launch_bounds__(256)
void softmax_rows()
{
    __shared__ float redMax[8];
    __shared__ float redSum[8];

    float* row = g_scores + (size_t)blockIdx.x * NSENT_;
    const int t = threadIdx.x;

    float2 v = reinterpret_cast<float2*>(row)[t];

    float m = fmaxf(v.x, v.y);
#pragma unroll
    for (int o = 16; o > 0; o >>= 1)
        m = fmaxf(m, __shfl_xor_sync(0xffffffffu, m, o));
    if ((t & 31) == 0) redMax[t >> 5] = m;
    __syncthreads();
    float mAll = redMax[0];
#pragma unroll
    for (int i = 1; i < 8; i++) mAll = fmaxf(mAll, redMax[i]);

    float e0 = expf(v.x - mAll);
    float e1 = expf(v.y - mAll);
    float s = e0 + e1;
#pragma unroll
    for (int o = 16; o > 0; o >>= 1)
        s += __shfl_xor_sync(0xffffffffu, s, o);
    if ((t & 31) == 0) redSum[t >> 5] = s;
    __syncthreads();
    float sAll = 0.f;
#pragma unroll
    for (int i = 0; i < 8; i++) sAll += redSum[i];

    const float inv = 1.0f / sAll;
    reinterpret_cast<float2*>(row)[t] = make_float2(e0 * inv, e1 * inv);
}

// ---------------------------------------------------------------------------
extern "C" void kernel_launch(void* const* d_in, const int* in_sizes, int n_in,
                              void* d_out, int out_size)
{
    (void)out_size;
    const float* word = nullptr;
    const float* sent = nullptr;
    const float* W    = nullptr;
    for (int i = 0; i < n_in; i++) {
        if      (in_sizes[i] == B_ * S_ * E_)     word = (const float*)d_in[i];
        else if (in_sizes[i] == B_ * NSENT_ * E_) sent = (const float*)d_in[i];
        else if (in_sizes[i] == E_ * E_)          W    = (const float*)d_in[i];
    }

    float* out  = (float*)d_out;
    float* comb = out;                                   // (8, 2048, 2048)
    float* gout = out + (size_t)B_ * S_ * 2 * E_;        // (8, 2048, 1024)

    dim3 blk(NTHREADS);

    // 1) w = word @ W^T  -> combination[:, :, 0:1024]
    //    M=16384 (b,s flattened), N=1024, K=1024
    sgemm_nt<<<dim3(E_ / TILE_N, (B_ * S_) / TILE_M, 1), blk>>>(
        word, W, comb,
        /*lda*/ E_, /*ldb*/ E_, /*ldc*/ 2 * E_, /*K*/ E_,
        0, 0, 0);

    // 2) scores[b] = w[b] @ sent[b]^T  -> g_scores   (M=2048, N=512, K=1024)
    sgemm_nt<<<dim3(NSENT_ / TILE_N, S_ / TILE_M, B_), blk>>>(
        comb, sent, nullptr /* -> g_scores */,
        /*lda*/ 2 * E_, /*ldb*/ E_, /*ldc*/ NSENT_, /*K*/ E_,
        (size_t)S_ * 2 * E_, (size_t)NSENT_ * E_, (size_t)S_ * NSENT_);

    // 3) softmax over the 512 sentence scores, per (b,s) row
    softmax_rows<<<B_ * S_, 256>>>();

    // 4) g[b] = att[b] @ sent[b]  -> combination[:, :, 1024:2048] AND g output
    //    M=2048, N=1024, K=512
    sgemm_nn_dual<<<dim3(E_ / TILE_N, S_ / TILE_M, B_), blk>>>(
        nullptr /* g_scores */, sent, comb + E_, gout,
        /*lda*/ NSENT_, /*ldb*/ E_, /*ldc1*/ 2 * E_, /*ldc2*/ E_, /*K*/ NSENT_,
        (size_t)S_ * NSENT_, (size_t)NSENT_ * E_, (size_t)S_ * 2 * E_, (size_t)S_ * E_);
}

// round 5
// speedup vs baseline: 1.4984x; 1.4984x over previous
#include <cuda_runtime.h>
#include <cstdint>
#include <cstddef>

// ---------------------------------------------------------------------------
// word (8,2048,1024) f32, sent (8,512,1024) f32, W (1024,1024) f32
// out: combination (8,2048,2048) then g (8,2048,1024)
// All three GEMMs: mma.sync m16n8k8 tf32 with 3xTF32 error compensation
// (valid on plain sm_103 target -- tcgen05 is NOT, the harness compiles
//  PTX for sm_103 without the 'a' feature suffix).
// ---------------------------------------------------------------------------

#define B_      8
#define S_      2048
#define NS_     512
#define E_      1024

#define BM 128
#define BN 128
#define BK 16
#define NTHREADS 256
#define PADLD 20                         // floats per smem row (conflict-free)
#define TILE_FLOATS (128 * PADLD)        // 2560 floats per operand tile
#define STAGE_FLOATS (2 * TILE_FLOATS)   // A tile + B tile
#define NSTAGE 3
#define DYN_SMEM (NSTAGE * STAGE_FLOATS * 4)   // 61440 B

__device__ float g_scores[B_ * S_ * NS_];   // 32 MB
__device__ float g_sentT [B_ * E_ * NS_];   // 16 MB

// ---------------------------------------------------------------------------
__device__ __forceinline__ uint32_t smem_u32(const void* p) {
    uint32_t a;
    asm("{ .reg .u64 t; cvta.to.shared.u64 t, %1; cvt.u32.u64 %0, t; }"
        : "=r"(a) : "l"(p));
    return a;
}

#define CP_ASYNC16(sm_addr, gptr) \
    asm volatile("cp.async.cg.shared.global [%0], [%1], 16;" \
                 :: "r"(sm_addr), "l"(gptr) : "memory")
#define CP_COMMIT() asm volatile("cp.async.commit_group;" ::: "memory")
#define CP_WAIT2()  asm volatile("cp.async.wait_group 2;" ::: "memory")

__device__ __forceinline__ void mma_tf32(float* c, const uint32_t* a,
                                         const uint32_t* b) {
    asm volatile(
        "mma.sync.aligned.m16n8k8.row.col.f32.tf32.tf32.f32 "
        "{%0,%1,%2,%3}, {%4,%5,%6,%7}, {%8,%9}, {%0,%1,%2,%3};"
        : "+f"(c[0]), "+f"(c[1]), "+f"(c[2]), "+f"(c[3])
        : "r"(a[0]), "r"(a[1]), "r"(a[2]), "r"(a[3]), "r"(b[0]), "r"(b[1]));
}

__device__ __forceinline__ uint32_t hi_bits(float x) {
    return __float_as_uint(x) & 0xFFFFE000u;
}
__device__ __forceinline__ uint32_t lo_bits(float x, uint32_t hb) {
    return __float_as_uint(x - __uint_as_float(hb));
}

// ---------------------------------------------------------------------------
// C[m,n] = sum_k A[m,k] * B[n,k]  (NT, both K-contiguous), 3xTF32.
// Block 128x128, BK=16, 3-stage cp.async pipeline. Optional dual output C2.
// ---------------------------------------------------------------------------
__global__ __launch_bounds__(NTHREADS, 1)
void gemm3x_nt(const float* __restrict__ A, const float* __restrict__ Bm,
               float* __restrict__ C, float* __restrict__ C2,
               int lda, int ldb, int ldc, int ldc2, int K,
               size_t aB, size_t bB, size_t cB, size_t c2B)
{
    extern __shared__ float sm[];

    const int tid  = threadIdx.x;
    const int wid  = tid >> 5;
    const int lane = tid & 31;
    const int wm   = wid & 3;     // warp M offset: 32*wm
    const int wn   = wid >> 2;    // warp N offset: 64*wn
    const int lr   = lane >> 2;   // 0..7
    const int lc   = lane & 3;    // 0..3

    const float* Ag = A  + (size_t)blockIdx.z * aB + (size_t)blockIdx.y * BM * lda;
    const float* Bg = Bm + (size_t)blockIdx.z * bB + (size_t)blockIdx.x * BN * ldb;

    // loader mapping: 512 float4 slots per tile, 2 per thread per tile
    const int ldRow0 = tid >> 2;              // slot tid
    const int ldC0   = (tid & 3) * 4;
    const int ldRow1 = (tid + 256) >> 2;      // slot tid+256
    const int ldC1   = ldC0;                  // (tid+256)&3 == tid&3

    float acc[2][8][4];
#pragma unroll
    for (int i = 0; i < 2; i++)
#pragma unroll
        for (int j = 0; j < 8; j++)
#pragma unroll
            for (int q = 0; q < 4; q++) acc[i][j][q] = 0.f;

    const int NCH = K / BK;

    // ---- prologue: prefetch stages 0..2 -----------------------------------
#pragma unroll
    for (int c = 0; c < NSTAGE; c++) {
        float* s = sm + c * STAGE_FLOATS;
        const int k0 = c * BK;
        CP_ASYNC16(smem_u32(s + ldRow0 * PADLD + ldC0),
                   Ag + (size_t)ldRow0 * lda + k0 + ldC0);
        CP_ASYNC16(smem_u32(s + ldRow1 * PADLD + ldC1),
                   Ag + (size_t)ldRow1 * lda + k0 + ldC1);
        CP_ASYNC16(smem_u32(s + TILE_FLOATS + ldRow0 * PADLD + ldC0),
                   Bg + (size_t)ldRow0 * ldb + k0 + ldC0);
        CP_ASYNC16(smem_u32(s + TILE_FLOATS + ldRow1 * PADLD + ldC1),
                   Bg + (size_t)ldRow1 * ldb + k0 + ldC1);
        CP_COMMIT();
    }

    // ---- main loop --------------------------------------------------------
    int stage = 0;
    for (int c = 0; c < NCH; c++) {
        CP_WAIT2();             // chunk c has landed
        __syncthreads();

        const float* As = sm + stage * STAGE_FLOATS;
        const float* Bs = As + TILE_FLOATS;

#pragma unroll
        for (int k8 = 0; k8 < 2; k8++) {
            const int ko = k8 * 8;

            uint32_t ah[2][4], al[2][4];
#pragma unroll
            for (int i = 0; i < 2; i++) {
                const int m0 = wm * 32 + i * 16;
                float x0 = As[(m0 + lr)     * PADLD + ko + lc];
                float x1 = As[(m0 + 8 + lr) * PADLD + ko + lc];
                float x2 = As[(m0 + lr)     * PADLD + ko + 4 + lc];
                float x3 = As[(m0 + 8 + lr) * PADLD + ko + 4 + lc];
                ah[i][0] = hi_bits(x0); al[i][0] = lo_bits(x0, ah[i][0]);
                ah[i][1] = hi_bits(x1); al[i][1] = lo_bits(x1, ah[i][1]);
                ah[i][2] = hi_bits(x2); al[i][2] = lo_bits(x2, ah[i][2]);
                ah[i][3] = hi_bits(x3); al[i][3] = lo_bits(x3, ah[i][3]);
            }

            uint32_t bh[8][2], bl[8][2];
#pragma unroll
            for (int j = 0; j < 8; j++) {
                const int n0 = wn * 64 + j * 8;
                float y0 = Bs[(n0 + lr) * PADLD + ko + lc];
                float y1 = Bs[(n0 + lr) * PADLD + ko + 4 + lc];
                bh[j][0] = hi_bits(y0); bl[j][0] = lo_bits(y0, bh[j][0]);
                bh[j][1] = hi_bits(y1); bl[j][1] = lo_bits(y1, bh[j][1]);
            }

#pragma unroll
            for (int i = 0; i < 2; i++)
#pragma unroll
                for (int j = 0; j < 8; j++) {
                    mma_tf32(acc[i][j], ah[i], bh[j]);
                    mma_tf32(acc[i][j], ah[i], bl[j]);
                    mma_tf32(acc[i][j], al[i], bh[j]);
                }
        }

        __syncthreads();        // everyone done reading `stage`

        const int cn = c + NSTAGE;
        if (cn < NCH) {         // refill this stage
            float* s = sm + stage * STAGE_FLOATS;
            const int k0 = cn * BK;
            CP_ASYNC16(smem_u32(s + ldRow0 * PADLD + ldC0),
                       Ag + (size_t)ldRow0 * lda + k0 + ldC0);
            CP_ASYNC16(smem_u32(s + ldRow1 * PADLD + ldC1),
                       Ag + (size_t)ldRow1 * lda + k0 + ldC1);
            CP_ASYNC16(smem_u32(s + TILE_FLOATS + ldRow0 * PADLD + ldC0),
                       Bg + (size_t)ldRow0 * ldb + k0 + ldC0);
            CP_ASYNC16(smem_u32(s + TILE_FLOATS + ldRow1 * PADLD + ldC1),
                       Bg + (size_t)ldRow1 * ldb + k0 + ldC1);
        }
        CP_COMMIT();            // keep group count in lockstep with waits

        stage = stage + 1 == NSTAGE ? 0 : stage + 1;
    }

    // ---- epilogue ---------------------------------------------------------
    float* Cb  = C + (size_t)blockIdx.z * cB + (size_t)blockIdx.x * BN;
    float* C2b = C2 ? C2 + (size_t)blockIdx.z * c2B + (size_t)blockIdx.x * BN
                    : nullptr;
#pragma unroll
    for (int i = 0; i < 2; i++) {
        const size_t mTop = (size_t)blockIdx.y * BM + wm * 32 + i * 16 + lr;
#pragma unroll
        for (int j = 0; j < 8; j++) {
            const int n0 = wn * 64 + j * 8 + 2 * lc;
            float2 v0 = make_float2(acc[i][j][0], acc[i][j][1]);
            float2 v1 = make_float2(acc[i][j][2], acc[i][j][3]);
            *(float2*)(Cb + mTop * ldc + n0)       = v0;
            *(float2*)(Cb + (mTop + 8) * ldc + n0) = v1;
            if (C2b) {
                *(float2*)(C2b + mTop * ldc2 + n0)       = v0;
                *(float2*)(C2b + (mTop + 8) * ldc2 + n0) = v1;
            }
        }
    }
}

// ---------------------------------------------------------------------------
// sent (b, 512, 1024) -> g_sentT (b, 1024, 512)
// ---------------------------------------------------------------------------
__global__ __launch_bounds__(256)
void transpose_sent(const float* __restrict__ sent, float* __restrict__ out)
{
    __shared__ float t[32][33];
    const int b  = blockIdx.z;
    const int n0 = blockIdx.y * 32;
    const int e0 = blockIdx.x * 32;
    const int x = threadIdx.x, y = threadIdx.y;

    const float* src = sent + ((size_t)b * NS_ + n0) * E_ + e0;
#pragma unroll
    for (int k = 0; k < 4; k++)
        t[y + 8 * k][x] = src[(size_t)(y + 8 * k) * E_ + x];
    __syncthreads();
    float* dst = out + ((size_t)b * E_ + e0) * NS_ + n0;
#pragma unroll
    for (int k = 0; k < 4; k++)
        dst[(size_t)(y + 8 * k) * NS_ + x] = t[x][y + 8 * k];
}

// ---------------------------------------------------------------------------
// In-place stable softmax over last dim (512) of g_scores, one block per row.
// ---------------------------------------------------------------------------
__global__ __launch_bounds__(256)
void softmax_rows()
{
    __shared__ float redMax[8];
    __shared__ float redSum[8];

    float* row = g_scores + (size_t)blockIdx.x * NS_;
    const int t = threadIdx.x;

    float2 v = reinterpret_cast<float2*>(row)[t];

    float m = fmaxf(v.x, v.y);
#pragma unroll
    for (int o = 16; o > 0; o >>= 1)
        m = fmaxf(m, __shfl_xor_sync(0xffffffffu, m, o));
    if ((t & 31) == 0) redMax[t >> 5] = m;
    __syncthreads();
    float mAll = redMax[0];
#pragma unroll
    for (int i = 1; i < 8; i++) mAll = fmaxf(mAll, redMax[i]);

    float e0 = expf(v.x - mAll);
    float e1 = expf(v.y - mAll);
    float s = e0 + e1;
#pragma unroll
    for (int o = 16; o > 0; o >>= 1)
        s += __shfl_xor_sync(0xffffffffu, s, o);
    if ((t & 31) == 0) redSum[t >> 5] = s;
    __syncthreads();
    float sAll = 0.f;
#pragma unroll
    for (int i = 0; i < 8; i++) sAll += redSum[i];

    const float inv = 1.0f / sAll;
    reinterpret_cast<float2*>(row)[t] = make_float2(e0 * inv, e1 * inv);
}

// ---------------------------------------------------------------------------
extern "C" void kernel_launch(void* const* d_in, const int* in_sizes, int n_in,
                              void* d_out, int out_size)
{
    (void)out_size;
    const float* word = nullptr;
    const float* sent = nullptr;
    const float* W    = nullptr;
    for (int i = 0; i < n_in; i++) {
        if      (in_sizes[i] == B_ * S_ * E_)  word = (const float*)d_in[i];
        else if (in_sizes[i] == B_ * NS_ * E_) sent = (const float*)d_in[i];
        else if (in_sizes[i] == E_ * E_)       W    = (const float*)d_in[i];
    }

    float* out  = (float*)d_out;
    float* comb = out;                               // (8, 2048, 2048)
    float* gout = out + (size_t)B_ * S_ * 2 * E_;    // (8, 2048, 1024)

    float *scores = nullptr, *sentT = nullptr;
    cudaGetSymbolAddress((void**)&scores, g_scores);
    cudaGetSymbolAddress((void**)&sentT,  g_sentT);

    cudaFuncSetAttribute(gemm3x_nt,
                         cudaFuncAttributeMaxDynamicSharedMemorySize, DYN_SMEM);

    // 0) sentT[b] = sent[b]^T
    transpose_sent<<<dim3(E_ / 32, NS_ / 32, B_), dim3(32, 8)>>>(sent, sentT);

    // 1) w = word @ W^T -> combination[:, :, 0:1024]  (M=16384, N=1024, K=1024)
    gemm3x_nt<<<dim3(E_ / BN, (B_ * S_) / BM, 1), NTHREADS, DYN_SMEM>>>(
        word, W, comb, nullptr,
        E_, E_, 2 * E_, 0, E_,
        0, 0, 0, 0);

    // 2) scores[b] = w[b] @ sent[b]^T -> g_scores     (M=2048, N=512, K=1024)
    gemm3x_nt<<<dim3(NS_ / BN, S_ / BM, B_), NTHREADS, DYN_SMEM>>>(
        comb, sent, scores, nullptr,
        2 * E_, E_, NS_, 0, E_,
        (size_t)S_ * 2 * E_, (size_t)NS_ * E_, (size_t)S_ * NS_, 0);

    // 3) softmax over 512 sentence scores per (b,s) row
    softmax_rows<<<B_ * S_, 256>>>();

    // 4) g[b] = att[b] @ sentT[b]^T -> comb 2nd half AND g  (M=2048, N=1024, K=512)
    gemm3x_nt<<<dim3(E_ / BN, S_ / BM, B_), NTHREADS, DYN_SMEM>>>(
        scores, sentT, comb + E_, gout,
        NS_, NS_, 2 * E_, E_, NS_,
        (size_t)S_ * NS_, (size_t)NS_ * E_, (size_t)S_ * 2 * E_, (size_t)S_ * E_);
}

// round 6
// speedup vs baseline: 2.1577x; 1.4400x over previous
#include <cuda_runtime.h>
#include <cuda_fp16.h>
#include <cstdint>
#include <cstddef>

// ---------------------------------------------------------------------------
// word (8,2048,1024) f32, sent (8,512,1024) f32, W (1024,1024) f32
// out: combination (8,2048,2048) then g (8,2048,1024)
// All GEMMs: mma.sync m16n8k16 fp16 with 2-way fp16 split, 3-term product
// (h0*g0 exact in fp32; dropped h1*g1 ~ 2^-22). ~2x the tf32 mma rate.
// ---------------------------------------------------------------------------

#define B_      8
#define S_      2048
#define NS_     512
#define E_      1024

#define BM 128
#define BN 128
#define BK 32
#define NTHREADS 256

#define HP 40                        // halves per smem row (80B, ldmatrix conflict-free)
#define TILE_H (128 * HP)            // 5120 halves per tile
#define STAGE_H (4 * TILE_H)         // Ah0 Ah1 Bh0 Bh1
#define STAGE_BYTES (STAGE_H * 2)    // 40960
#define DYN_SMEM (2 * STAGE_BYTES)   // 81920

__device__ float g_scores[B_ * S_ * NS_];   // 32 MB
__device__ float g_sentT [B_ * E_ * NS_];   // 16 MB

// ---------------------------------------------------------------------------
__device__ __forceinline__ uint32_t smem_u32(const void* p) {
    uint32_t a;
    asm("{ .reg .u64 t; cvta.to.shared.u64 t, %1; cvt.u32.u64 %0, t; }"
        : "=r"(a) : "l"(p));
    return a;
}

#define LDMX4(r0, r1, r2, r3, addr)                                           \
    asm volatile("ldmatrix.sync.aligned.m8n8.x4.shared.b16 {%0,%1,%2,%3}, [%4];" \
                 : "=r"(r0), "=r"(r1), "=r"(r2), "=r"(r3) : "r"(addr))

__device__ __forceinline__ void mma16816(float* c, const uint32_t* a,
                                         const uint32_t* b) {
    asm volatile(
        "mma.sync.aligned.m16n8k16.row.col.f32.f16.f16.f32 "
        "{%0,%1,%2,%3}, {%4,%5,%6,%7}, {%8,%9}, {%0,%1,%2,%3};"
        : "+f"(c[0]), "+f"(c[1]), "+f"(c[2]), "+f"(c[3])
        : "r"(a[0]), "r"(a[1]), "r"(a[2]), "r"(a[3]), "r"(b[0]), "r"(b[1]));
}

// ---------------------------------------------------------------------------
// C[m,n] = sum_k A[m,k] * B[n,k]  (NT, K-contiguous operands), fp16 3-term.
// Block 128x128, BK=32, 2-stage reg-staged double buffer. Optional dual C2.
// ---------------------------------------------------------------------------
__global__ __launch_bounds__(NTHREADS, 1)
void gemm3h_nt(const float* __restrict__ A, const float* __restrict__ Bm,
               float* __restrict__ C, float* __restrict__ C2,
               int lda, int ldb, int ldc, int ldc2, int K,
               size_t aB, size_t bB, size_t cB, size_t c2B)
{
    extern __shared__ __half smh[];

    const int tid  = threadIdx.x;
    const int wid  = tid >> 5;
    const int lane = tid & 31;
    const int wm   = wid & 3;      // M warp offset 32*wm
    const int wn   = wid >> 2;     // N warp offset 64*wn
    const int lr   = lane >> 2;    // 0..7  (acc row within 8)
    const int lc   = lane & 3;     // 0..3  (acc col pair)

    // loader mapping: 2 threads per row, each covers 16 of the 32 k-floats
    const int lrow = tid >> 1;
    const int lkh  = (tid & 1) * 16;

    const float* Ag = A  + (size_t)blockIdx.z * aB
                         + ((size_t)blockIdx.y * BM + lrow) * lda + lkh;
    const float* Bg = Bm + (size_t)blockIdx.z * bB
                         + ((size_t)blockIdx.x * BN + lrow) * ldb + lkh;

    // ldmatrix per-lane addressing
    const int msel = lane >> 3, mr = lane & 7;
    const int a_r = (msel & 1) * 8 + mr, a_c = (msel >> 1) * 8;
    const int b_r = (msel >> 1) * 8 + mr, b_c = (msel & 1) * 8;

    const uint32_t base_u = smem_u32(smh);
    uint32_t aAdr[2], bAdr[4];
#pragma unroll
    for (int i = 0; i < 2; i++)
        aAdr[i] = base_u + 2u * ((wm * 32 + i * 16 + a_r) * HP + a_c);
#pragma unroll
    for (int jp = 0; jp < 4; jp++)
        bAdr[jp] = base_u + 2u * (2 * TILE_H + (wn * 64 + jp * 16 + b_r) * HP + b_c);

    float acc[2][8][4];
#pragma unroll
    for (int i = 0; i < 2; i++)
#pragma unroll
        for (int j = 0; j < 8; j++)
#pragma unroll
            for (int q = 0; q < 4; q++) acc[i][j][q] = 0.f;

    const int NCH = K / BK;
    const int sts_pos = lrow * HP + lkh;      // half index within a tile

    // ---- preload chunk 0 --------------------------------------------------
    {
        float4 sa[4], sb[4];
#pragma unroll
        for (int q = 0; q < 4; q++) {
            sa[q] = *(const float4*)(Ag + 4 * q);
            sb[q] = *(const float4*)(Bg + 4 * q);
        }
        __half* st = smh;                      // stage 0
#pragma unroll
        for (int q = 0; q < 4; q++) {
            // A split
            __half2 h0a = __floats2half2_rn(sa[q].x, sa[q].y);
            __half2 h0b = __floats2half2_rn(sa[q].z, sa[q].w);
            float2 ba = __half22float2(h0a), bb = __half22float2(h0b);
            __half2 h1a = __floats2half2_rn(sa[q].x - ba.x, sa[q].y - ba.y);
            __half2 h1b = __floats2half2_rn(sa[q].z - bb.x, sa[q].w - bb.y);
            __half2* p0 = (__half2*)(st + sts_pos + 4 * q);
            __half2* p1 = (__half2*)(st + TILE_H + sts_pos + 4 * q);
            p0[0] = h0a; p0[1] = h0b; p1[0] = h1a; p1[1] = h1b;
            // B split
            __half2 g0a = __floats2half2_rn(sb[q].x, sb[q].y);
            __half2 g0b = __floats2half2_rn(sb[q].z, sb[q].w);
            float2 ca = __half22float2(g0a), cb = __half22float2(g0b);
            __half2 g1a = __floats2half2_rn(sb[q].x - ca.x, sb[q].y - ca.y);
            __half2 g1b = __floats2half2_rn(sb[q].z - cb.x, sb[q].w - cb.y);
            __half2* q0 = (__half2*)(st + 2 * TILE_H + sts_pos + 4 * q);
            __half2* q1 = (__half2*)(st + 3 * TILE_H + sts_pos + 4 * q);
            q0[0] = g0a; q0[1] = g0b; q1[0] = g1a; q1[1] = g1b;
        }
    }
    __syncthreads();

    // ---- main loop --------------------------------------------------------
    for (int c = 0; c < NCH; c++) {
        const int s = c & 1;
        const bool hasNext = (c + 1 < NCH);

        float4 sa[4], sb[4];
        if (hasNext) {
            const float* ap = Ag + (size_t)(c + 1) * BK;
            const float* bp = Bg + (size_t)(c + 1) * BK;
#pragma unroll
            for (int q = 0; q < 4; q++) {
                sa[q] = *(const float4*)(ap + 4 * q);
                sb[q] = *(const float4*)(bp + 4 * q);
            }
        }

        const uint32_t so = (uint32_t)s * STAGE_BYTES;
#pragma unroll
        for (int ks = 0; ks < 2; ks++) {
            const uint32_t ko = so + ks * 32u;   // 16 halves = 32 bytes

            uint32_t a0[2][4], a1[2][4];
#pragma unroll
            for (int i = 0; i < 2; i++) {
                LDMX4(a0[i][0], a0[i][1], a0[i][2], a0[i][3], aAdr[i] + ko);
                LDMX4(a1[i][0], a1[i][1], a1[i][2], a1[i][3],
                      aAdr[i] + ko + 2u * TILE_H);
            }
            uint32_t b0[8][2], b1[8][2];
#pragma unroll
            for (int jp = 0; jp < 4; jp++) {
                LDMX4(b0[2 * jp][0], b0[2 * jp][1], b0[2 * jp + 1][0],
                      b0[2 * jp + 1][1], bAdr[jp] + ko);
                LDMX4(b1[2 * jp][0], b1[2 * jp][1], b1[2 * jp + 1][0],
                      b1[2 * jp + 1][1], bAdr[jp] + ko + 2u * TILE_H);
            }
#pragma unroll
            for (int i = 0; i < 2; i++)
#pragma unroll
                for (int j = 0; j < 8; j++) {
                    mma16816(acc[i][j], a0[i], b0[j]);
                    mma16816(acc[i][j], a0[i], b1[j]);
                    mma16816(acc[i][j], a1[i], b0[j]);
                }
        }

        if (hasNext) {
            __half* st = smh + (s ^ 1) * STAGE_H;
#pragma unroll
            for (int q = 0; q < 4; q++) {
                __half2 h0a = __floats2half2_rn(sa[q].x, sa[q].y);
                __half2 h0b = __floats2half2_rn(sa[q].z, sa[q].w);
                float2 ba = __half22float2(h0a), bb = __half22float2(h0b);
                __half2 h1a = __floats2half2_rn(sa[q].x - ba.x, sa[q].y - ba.y);
                __half2 h1b = __floats2half2_rn(sa[q].z - bb.x, sa[q].w - bb.y);
                __half2* p0 = (__half2*)(st + sts_pos + 4 * q);
                __half2* p1 = (__half2*)(st + TILE_H + sts_pos + 4 * q);
                p0[0] = h0a; p0[1] = h0b; p1[0] = h1a; p1[1] = h1b;

                __half2 g0a = __floats2half2_rn(sb[q].x, sb[q].y);
                __half2 g0b = __floats2half2_rn(sb[q].z, sb[q].w);
                float2 ca = __half22float2(g0a), cb = __half22float2(g0b);
                __half2 g1a = __floats2half2_rn(sb[q].x - ca.x, sb[q].y - ca.y);
                __half2 g1b = __floats2half2_rn(sb[q].z - cb.x, sb[q].w - cb.y);
                __half2* q0 = (__half2*)(st + 2 * TILE_H + sts_pos + 4 * q);
                __half2* q1 = (__half2*)(st + 3 * TILE_H + sts_pos + 4 * q);
                q0[0] = g0a; q0[1] = g0b; q1[0] = g1a; q1[1] = g1b;
            }
        }
        __syncthreads();
    }

    // ---- epilogue ---------------------------------------------------------
    float* Cb  = C + (size_t)blockIdx.z * cB + (size_t)blockIdx.x * BN;
    float* C2b = C2 ? C2 + (size_t)blockIdx.z * c2B + (size_t)blockIdx.x * BN
                    : nullptr;
#pragma unroll
    for (int i = 0; i < 2; i++) {
        const size_t mTop = (size_t)blockIdx.y * BM + wm * 32 + i * 16 + lr;
#pragma unroll
        for (int j = 0; j < 8; j++) {
            const int n0 = wn * 64 + j * 8 + 2 * lc;
            float2 v0 = make_float2(acc[i][j][0], acc[i][j][1]);
            float2 v1 = make_float2(acc[i][j][2], acc[i][j][3]);
            *(float2*)(Cb + mTop * ldc + n0)       = v0;
            *(float2*)(Cb + (mTop + 8) * ldc + n0) = v1;
            if (C2b) {
                *(float2*)(C2b + mTop * ldc2 + n0)       = v0;
                *(float2*)(C2b + (mTop + 8) * ldc2 + n0) = v1;
            }
        }
    }
}

// ---------------------------------------------------------------------------
// sent (b, 512, 1024) -> g_sentT (b, 1024, 512)
// ---------------------------------------------------------------------------
__global__ __launch_bounds__(256)
void transpose_sent(const float* __restrict__ sent, float* __restrict__ out)
{
    __shared__ float t[32][33];
    const int b  = blockIdx.z;
    const int n0 = blockIdx.y * 32;
    const int e0 = blockIdx.x * 32;
    const int x = threadIdx.x, y = threadIdx.y;

    const float* src = sent + ((size_t)b * NS_ + n0) * E_ + e0;
#pragma unroll
    for (int k = 0; k < 4; k++)
        t[y + 8 * k][x] = src[(size_t)(y + 8 * k) * E_ + x];
    __syncthreads();
    float* dst = out + ((size_t)b * E_ + e0) * NS_ + n0;
#pragma unroll
    for (int k = 0; k < 4; k++)
        dst[(size_t)(y + 8 * k) * NS_ + x] = t[x][y + 8 * k];
}

// ---------------------------------------------------------------------------
// In-place stable softmax over last dim (512) of g_scores, one block per row.
// ---------------------------------------------------------------------------
__global__ __launch_bounds__(256)
void softmax_rows()
{
    __shared__ float redMax[8];
    __shared__ float redSum[8];

    float* row = g_scores + (size_t)blockIdx.x * NS_;
    const int t = threadIdx.x;

    float2 v = reinterpret_cast<float2*>(row)[t];

    float m = fmaxf(v.x, v.y);
#pragma unroll
    for (int o = 16; o > 0; o >>= 1)
        m = fmaxf(m, __shfl_xor_sync(0xffffffffu, m, o));
    if ((t & 31) == 0) redMax[t >> 5] = m;
    __syncthreads();
    float mAll = redMax[0];
#pragma unroll
    for (int i = 1; i < 8; i++) mAll = fmaxf(mAll, redMax[i]);

    float e0 = expf(v.x - mAll);
    float e1 = expf(v.y - mAll);
    float s = e0 + e1;
#pragma unroll
    for (int o = 16; o > 0; o >>= 1)
        s += __shfl_xor_sync(0xffffffffu, s, o);
    if ((t & 31) == 0) redSum[t >> 5] = s;
    __syncthreads();
    float sAll = 0.f;
#pragma unroll
    for (int i = 0; i < 8; i++) sAll += redSum[i];

    const float inv = 1.0f / sAll;
    reinterpret_cast<float2*>(row)[t] = make_float2(e0 * inv, e1 * inv);
}

// ---------------------------------------------------------------------------
extern "C" void kernel_launch(void* const* d_in, const int* in_sizes, int n_in,
                              void* d_out, int out_size)
{
    (void)out_size;
    const float* word = nullptr;
    const float* sent = nullptr;
    const float* W    = nullptr;
    for (int i = 0; i < n_in; i++) {
        if      (in_sizes[i] == B_ * S_ * E_)  word = (const float*)d_in[i];
        else if (in_sizes[i] == B_ * NS_ * E_) sent = (const float*)d_in[i];
        else if (in_sizes[i] == E_ * E_)       W    = (const float*)d_in[i];
    }

    float* out  = (float*)d_out;
    float* comb = out;                               // (8, 2048, 2048)
    float* gout = out + (size_t)B_ * S_ * 2 * E_;    // (8, 2048, 1024)

    float *scores = nullptr, *sentT = nullptr;
    cudaGetSymbolAddress((void**)&scores, g_scores);
    cudaGetSymbolAddress((void**)&sentT,  g_sentT);

    cudaFuncSetAttribute(gemm3h_nt,
                         cudaFuncAttributeMaxDynamicSharedMemorySize, DYN_SMEM);

    // 0) sentT[b] = sent[b]^T
    transpose_sent<<<dim3(E_ / 32, NS_ / 32, B_), dim3(32, 8)>>>(sent, sentT);

    // 1) w = word @ W^T -> combination[:, :, 0:1024]  (M=16384, N=1024, K=1024)
    gemm3h_nt<<<dim3(E_ / BN, (B_ * S_) / BM, 1), NTHREADS, DYN_SMEM>>>(
        word, W, comb, nullptr,
        E_, E_, 2 * E_, 0, E_,
        0, 0, 0, 0);

    // 2) scores[b] = w[b] @ sent[b]^T -> g_scores     (M=2048, N=512, K=1024)
    gemm3h_nt<<<dim3(NS_ / BN, S_ / BM, B_), NTHREADS, DYN_SMEM>>>(
        comb, sent, scores, nullptr,
        2 * E_, E_, NS_, 0, E_,
        (size_t)S_ * 2 * E_, (size_t)NS_ * E_, (size_t)S_ * NS_, 0);

    // 3) softmax over 512 sentence scores per (b,s) row
    softmax_rows<<<B_ * S_, 256>>>();

    // 4) g[b] = att[b] @ sentT[b]^T -> comb 2nd half AND g  (M=2048, N=1024, K=512)
    gemm3h_nt<<<dim3(E_ / BN, S_ / BM, B_), NTHREADS, DYN_SMEM>>>(
        scores, sentT, comb + E_, gout,
        NS_, NS_, 2 * E_, E_, NS_,
        (size_t)S_ * NS_, (size_t)NS_ * E_, (size_t)S_ * 2 * E_, (size_t)S_ * E_);
}